// round 7
// baseline (speedup 1.0000x reference)
#include <cuda_runtime.h>

// GeneralizedCrossEntropy — only spatial columns 0..20 of each batch are used,
// and target values (column indices) are < C=21. Therefore the ENTIRE set of
// logits the kernel can ever touch is the static tile logits[:, :, 0:21]
// (16*21*21 floats = 28KB).
//
// R7: break the targets->logits dependent-load chain. Load the whole candidate
// tile into smem IN PARALLEL with the targets load (both issue at t=0, one
// DRAM round trip total instead of two chained ones), then select + softmax
// from smem.

#define GCE_B 16
#define GCE_C 21
#define GCE_HW (512 * 512)
#define GCE_Q 0.8f
#define ROW_PAD 25                    // 21 floats padded: conflict-free strided reads

__global__ void __launch_bounds__(GCE_B * 32, 1)
gce_kernel(const float* __restrict__ logits,
           const int* __restrict__ targets,
           float* __restrict__ out) {
    __shared__ float s_tile[GCE_B * GCE_C * ROW_PAD];  // [336][25] floats
    __shared__ int   s_pos[GCE_B];
    __shared__ float s_terms[GCE_B];

    const int k = blockIdx.x;            // 0..20  (output index)
    const int w = threadIdx.x >> 5;      // 0..15  (warp = batch b)
    const int lane = threadIdx.x & 31;

    // ---- Phase 1: all loads issued up front, one DRAM round trip ----
    // warp w, lane c<21 loads row (w*21+c) = logits[w, c, 0:24] as 6 float4
    if (lane < GCE_C) {
        const int row = w * GCE_C + lane;
        const float4* src = (const float4*)(logits + (long long)row * GCE_HW);
        float* dst = &s_tile[row * ROW_PAD];
#pragma unroll
        for (int j = 0; j < 6; j++) {
            float4 v = src[j];          // rows are 1MB apart: +24 floats is safe
            dst[j * 4 + 0] = v.x;
            dst[j * 4 + 1] = v.y;
            dst[j * 4 + 2] = v.z;
            dst[j * 4 + 3] = v.w;       // j=5 writes idx 20..23 < ROW_PAD
        }
    }
    // threads 0..15 load targets[b*HW + k] (independent of the tile loads)
    if (threadIdx.x < GCE_B) {
        int p = targets[threadIdx.x * GCE_HW + k];
        s_pos[threadIdx.x] = min(max(p, 0), GCE_C - 1);
    }
    __syncthreads();

    // ---- Phase 2: softmax-select from smem ----
    const int pos = s_pos[w];
    float e = 0.0f;
    if (lane < GCE_C) {
        e = expf(s_tile[(w * GCE_C + lane) * ROW_PAD + pos]);
    }
    float s = e;
#pragma unroll
    for (int off = 16; off > 0; off >>= 1)
        s += __shfl_xor_sync(0xFFFFFFFF, s, off);

    if (lane == k) {
        float d = e / s;
        s_terms[w] = (1.0f - __powf(d, GCE_Q)) / GCE_Q;
    }
    __syncthreads();

    // warp 0 reduces the 16 per-batch terms and writes out[k]
    if (threadIdx.x < 32) {
        float v = (lane < GCE_B) ? s_terms[lane] : 0.0f;
#pragma unroll
        for (int off = 8; off > 0; off >>= 1)
            v += __shfl_xor_sync(0xFFFFFFFF, v, off);
        if (lane == 0)
            out[k] = v * (1.0f / (float)GCE_B);
    }
}

extern "C" void kernel_launch(void* const* d_in, const int* in_sizes, int n_in,
                              void* d_out, int out_size) {
    const float* logits = (const float*)d_in[0];
    const int* targets = (const int*)d_in[1];
    float* out = (float*)d_out;

    gce_kernel<<<GCE_C, GCE_B * 32>>>(logits, targets, out);
}